// round 16
// baseline (speedup 1.0000x reference)
#include <cuda_runtime.h>
#include <cuda_fp16.h>
#include <math.h>
#include <stdio.h>

#define NATOMS 10000
#define NEDGES 64000
#define NB     128
#define NH     600
#define NG     50
#define NL     6
#define LOG2F_C 0.6931471805599453f
#define PI_F    3.14159265358979323846f

// ---------------- scratch (device globals; no allocation allowed) ----------------
__device__ float g_rbf [(size_t)NEDGES * NG];
__device__ float g_Ccut[NEDGES];
__device__ float g_h   [(size_t)NATOMS * NH];
__device__ float g_t1  [(size_t)NEDGES * NH];
__device__ float g_W   [(size_t)NEDGES * NH];
__device__ float g_hp  [(size_t)NATOMS * NH];
__device__ float g_agg [(size_t)NATOMS * NH];
__device__ float g_x   [(size_t)NATOMS * NH];
__device__ float g_pool[(size_t)NB * NH];
__device__ float g_cnt [NB];

__device__ __forceinline__ float ssp(float x) {
    return log1pf(expf(-fabsf(x))) + fmaxf(x, 0.0f) - LOG2F_C;
}

// fp16 MMA m16n8k16, fp32 accumulate
__device__ __forceinline__ void mma_f16(float* c, const unsigned* a, unsigned b0, unsigned b1) {
    asm volatile(
        "mma.sync.aligned.m16n8k16.row.col.f32.f16.f16.f32 "
        "{%0,%1,%2,%3}, {%4,%5,%6,%7}, {%8,%9}, {%0,%1,%2,%3};\n"
        : "+f"(c[0]), "+f"(c[1]), "+f"(c[2]), "+f"(c[3])
        : "r"(a[0]), "r"(a[1]), "r"(a[2]), "r"(a[3]), "r"(b0), "r"(b1));
}

__device__ __forceinline__ void ldm_x4(unsigned* r, unsigned addr) {
    asm volatile("ldmatrix.sync.aligned.m8n8.x4.shared.b16 {%0,%1,%2,%3}, [%4];"
                 : "=r"(r[0]), "=r"(r[1]), "=r"(r[2]), "=r"(r[3]) : "r"(addr));
}

__device__ __forceinline__ void ldm_x4_t(unsigned* r, unsigned addr) {
    asm volatile("ldmatrix.sync.aligned.m8n8.x4.trans.shared.b16 {%0,%1,%2,%3}, [%4];"
                 : "=r"(r[0]), "=r"(r[1]), "=r"(r[2]), "=r"(r[3]) : "r"(addr));
}

__device__ __forceinline__ unsigned pack_h2(float x, float y) {
    __half2 h = __floats2half2_rn(x, y);
    return *(unsigned*)&h;
}

// ---------------- edge geometry ----------------
__global__ void edge_geom_kernel(const float* __restrict__ pos,
                                 const int* __restrict__ ei,
                                 float* __restrict__ rbf,
                                 float* __restrict__ Ccut) {
    int e = blockIdx.x * blockDim.x + threadIdx.x;
    if (e >= NEDGES) return;
    int s = ei[e];
    int t = ei[NEDGES + e];
    float dx = pos[3*s+0] - pos[3*t+0];
    float dy = pos[3*s+1] - pos[3*t+1];
    float dz = pos[3*s+2] - pos[3*t+2];
    float d = sqrtf(dx*dx + dy*dy + dz*dz + 1e-12f);
    Ccut[e] = 0.5f * (cosf(d * (PI_F / 10.0f)) + 1.0f);
    const float delta = 10.0f / 49.0f;
    const float coeff = -0.5f / (delta * delta);
    #pragma unroll
    for (int g = 0; g < NG; g++) {
        float u = d - (float)g * delta;
        rbf[(size_t)e * NG + g] = expf(coeff * u * u);
    }
}

// ---------------- h init ----------------
__global__ void init_h_kernel(const int* __restrict__ z,
                              const float* __restrict__ emb,
                              float* __restrict__ h) {
    size_t idx = (size_t)blockIdx.x * blockDim.x + threadIdx.x;
    if (idx >= (size_t)NATOMS * NH) return;
    int n = (int)(idx / NH);
    int c = (int)(idx - (size_t)n * NH);
    h[idx] = emb[(size_t)z[n] * NH + c];
}

// ---------------- fp16 tensor-core GEMM, 128x128x16 tile, double-buffered ---
// C[M,N] = A[M,K] @ B[K,N], row-major global (fp32), fp16 smem tiles.
// As: half [m][k] pitch 24; A frags via ldmatrix.x4.
// Bs: half [k][n] pitch 136; B frags via ldmatrix.x4.trans (2 per k-tile).
// Two smem stages, ONE __syncthreads per k-tile:
//   iter i: LDG tile i+1 -> regs | ldmatrix+MMA from stage p | STS into stage p^1
// EPI 0: out=v+bias  1: out=ssp(v+bias)  2: out=(v+bias)*rowmul[row]  3: out=v
// EPI 4: acc[row,col] += v+bias  (residual)
#define LDA_H 24
#define LDB_H 136
#define A_ELEMS (128 * LDA_H)
#define B_ELEMS (16 * LDB_H)

template<int EPI>
__global__ __launch_bounds__(256, 2)
void gemm_tc(const float* __restrict__ A, const float* __restrict__ Bm,
             const float* __restrict__ bias, float* __restrict__ Cout,
             int M, int Nn, int K,
             const float* __restrict__ rowmul, float* __restrict__ accp)
{
    __shared__ __half As[2 * A_ELEMS];
    __shared__ __half Bs[2 * B_ELEMS];

    const int tid  = threadIdx.x;
    const int lane = tid & 31;
    const int warp = tid >> 5;
    const int wm = (warp >> 2) * 64;   // 0/64
    const int wn = (warp &  3) * 32;   // 0/32/64/96
    const int g = lane >> 2;
    const int t = lane & 3;
    const int m0 = blockIdx.y * 128;
    const int n0 = blockIdx.x * 128;

    float acc[4][4][4];
    #pragma unroll
    for (int i = 0; i < 4; i++)
        #pragma unroll
        for (int j = 0; j < 4; j++)
            #pragma unroll
            for (int r = 0; r < 4; r++) acc[i][j][r] = 0.0f;

    const bool kvec = ((K & 3) == 0);
    float4 aReg[2], bReg[2];

    // staging indices (constant)
    const int amI[2] = { tid >> 2, (tid + 256) >> 2 };
    const int at4[2] = { (tid & 3) << 2, ((tid + 256) & 3) << 2 };
    const int bkI[2] = { tid >> 5, (tid + 256) >> 5 };
    const int bn4[2] = { (tid & 31) << 2, ((tid + 256) & 31) << 2 };

    auto loadTile = [&](int kt) {
        #pragma unroll
        for (int i = 0; i < 2; i++) {
            int row = m0 + amI[i], col = kt + at4[i];
            float4 v = make_float4(0.f, 0.f, 0.f, 0.f);
            if (row < M) {
                if (kvec && col + 4 <= K) {
                    v = *(const float4*)&A[(size_t)row * K + col];
                } else {
                    const float* ap = &A[(size_t)row * K];
                    if (col + 0 < K) v.x = ap[col + 0];
                    if (col + 1 < K) v.y = ap[col + 1];
                    if (col + 2 < K) v.z = ap[col + 2];
                    if (col + 3 < K) v.w = ap[col + 3];
                }
            }
            aReg[i] = v;
            int brow = kt + bkI[i], bcol = n0 + bn4[i];
            float4 w = make_float4(0.f, 0.f, 0.f, 0.f);
            if (brow < K) {
                if (bcol + 4 <= Nn) {
                    w = *(const float4*)&Bm[(size_t)brow * Nn + bcol];
                } else {
                    const float* bp = &Bm[(size_t)brow * Nn];
                    if (bcol + 0 < Nn) w.x = bp[bcol + 0];
                    if (bcol + 1 < Nn) w.y = bp[bcol + 1];
                    if (bcol + 2 < Nn) w.z = bp[bcol + 2];
                    if (bcol + 3 < Nn) w.w = bp[bcol + 3];
                }
            }
            bReg[i] = w;
        }
    };

    auto commitTile = [&](int buf) {
        __half* ab = As + buf * A_ELEMS;
        __half* bb = Bs + buf * B_ELEMS;
        #pragma unroll
        for (int i = 0; i < 2; i++) {
            unsigned pa0 = pack_h2(aReg[i].x, aReg[i].y);
            unsigned pa1 = pack_h2(aReg[i].z, aReg[i].w);
            unsigned* ad = (unsigned*)&ab[amI[i] * LDA_H + at4[i]];
            ad[0] = pa0; ad[1] = pa1;
            unsigned pb0 = pack_h2(bReg[i].x, bReg[i].y);
            unsigned pb1 = pack_h2(bReg[i].z, bReg[i].w);
            unsigned* bd = (unsigned*)&bb[bkI[i] * LDB_H + bn4[i]];
            bd[0] = pb0; bd[1] = pb1;
        }
    };

    // fragment addresses, both buffers
    const int m_lane = wm + ((lane >> 3) & 1) * 8 + (lane & 7);
    const int k_offA = (lane >> 4) * 8;
    const unsigned aSm = (unsigned)__cvta_generic_to_shared(As);
    const unsigned aAddr0 = aSm + (unsigned)(m_lane * LDA_H + k_offA) * 2u;
    const unsigned aAddr1 = aAddr0 + (unsigned)A_ELEMS * 2u;
    const int bj = lane >> 3, br = lane & 7;
    const unsigned bSm = (unsigned)__cvta_generic_to_shared(Bs);
    const unsigned bAddr0 = bSm +
        (unsigned)((((bj & 1) * 8 + br) * LDB_H) + wn + ((bj >> 1) * 8)) * 2u;
    const unsigned bAddr1 = bAddr0 + (unsigned)B_ELEMS * 2u;

    loadTile(0);
    commitTile(0);
    __syncthreads();

    int p = 0;
    for (int k0 = 0; k0 < K; k0 += 16) {
        int kn = k0 + 16;
        const bool more = (kn < K);
        if (more) loadTile(kn);   // LDG in flight while we compute

        const unsigned aA = p ? aAddr1 : aAddr0;
        const unsigned bA = p ? bAddr1 : bAddr0;

        unsigned bfr[2][4];
        ldm_x4_t(bfr[0], bA);
        ldm_x4_t(bfr[1], bA + 16u * 2u);

        unsigned af[4][4];
        #pragma unroll
        for (int mf = 0; mf < 4; mf++)
            ldm_x4(af[mf], aA + (unsigned)(mf * 16 * LDA_H) * 2u);

        #pragma unroll
        for (int mf = 0; mf < 4; mf++)
            #pragma unroll
            for (int nf = 0; nf < 4; nf++)
                mma_f16(acc[mf][nf], af[mf],
                        bfr[nf >> 1][(nf & 1) * 2], bfr[nf >> 1][(nf & 1) * 2 + 1]);

        if (more) {
            commitTile(p ^ 1);
            __syncthreads();
            p ^= 1;
        }
    }

    // epilogue
    #pragma unroll
    for (int mf = 0; mf < 4; mf++) {
        #pragma unroll
        for (int nf = 0; nf < 4; nf++) {
            int rb = m0 + wm + mf * 16 + g;
            int cb = n0 + wn + nf * 8 + 2 * t;
            #pragma unroll
            for (int half = 0; half < 2; half++) {
                int mm = rb + half * 8;
                if (mm >= M) continue;
                float v0 = acc[mf][nf][half * 2 + 0];
                float v1 = acc[mf][nf][half * 2 + 1];
                float cm = (EPI == 2) ? rowmul[mm] : 0.0f;
                #pragma unroll
                for (int q = 0; q < 2; q++) {
                    int nn = cb + q;
                    if (nn >= Nn) continue;
                    float v = (q == 0) ? v0 : v1;
                    if (EPI == 0)      { v += bias[nn]; }
                    else if (EPI == 1) { v = ssp(v + bias[nn]); }
                    else if (EPI == 2) { v = (v + bias[nn]) * cm; }
                    else if (EPI == 4) { accp[(size_t)mm * Nn + nn] += v + bias[nn]; continue; }
                    Cout[(size_t)mm * Nn + nn] = v;
                }
            }
        }
    }
}

// ---------------- CFConv scatter (float4 vectorized) ----------------
__global__ void scatter_kernel(const int* __restrict__ ei,
                               const float* __restrict__ hp,
                               const float* __restrict__ W,
                               float* __restrict__ agg) {
    size_t idx = (size_t)blockIdx.x * blockDim.x + threadIdx.x;
    const int Q = NH / 4;  // 150
    if (idx >= (size_t)NEDGES * Q) return;
    int e = (int)(idx / Q);
    int c4 = (int)(idx - (size_t)e * Q) * 4;
    int s = ei[e];
    int t = ei[NEDGES + e];
    float4 hv = *(const float4*)&hp[(size_t)s * NH + c4];
    float4 wv = *(const float4*)&W[(size_t)e * NH + c4];
    float* dst = &agg[(size_t)t * NH + c4];
    atomicAdd(dst + 0, hv.x * wv.x);
    atomicAdd(dst + 1, hv.y * wv.y);
    atomicAdd(dst + 2, hv.z * wv.z);
    atomicAdd(dst + 3, hv.w * wv.w);
}

// ---------------- pooling ----------------
__global__ void pool_sum_kernel(const int* __restrict__ batch,
                                const float* __restrict__ h,
                                float* __restrict__ psum) {
    size_t idx = (size_t)blockIdx.x * blockDim.x + threadIdx.x;
    const int Q = NH / 4;
    if (idx >= (size_t)NATOMS * Q) return;
    int n = (int)(idx / Q);
    int c4 = (int)(idx - (size_t)n * Q) * 4;
    float4 hv = *(const float4*)&h[(size_t)n * NH + c4];
    float* dst = &psum[(size_t)batch[n] * NH + c4];
    atomicAdd(dst + 0, hv.x);
    atomicAdd(dst + 1, hv.y);
    atomicAdd(dst + 2, hv.z);
    atomicAdd(dst + 3, hv.w);
}

__global__ void pool_cnt_kernel(const int* __restrict__ batch, float* __restrict__ cnt) {
    int n = blockIdx.x * blockDim.x + threadIdx.x;
    if (n >= NATOMS) return;
    atomicAdd(&cnt[batch[n]], 1.0f);
}

__global__ void pool_div_kernel(float* __restrict__ psum, const float* __restrict__ cnt) {
    int idx = blockIdx.x * blockDim.x + threadIdx.x;
    if (idx >= NB * NH) return;
    int b = idx / NH;
    psum[idx] /= fmaxf(cnt[b], 1.0f);
}

// ---------------- host launcher ----------------
extern "C" void kernel_launch(void* const* d_in, const int* in_sizes, int n_in,
                              void* d_out, int out_size) {
    const int*   z        = (const int*)  d_in[0];
    const float* pos      = (const float*)d_in[1];
    const int*   batch    = (const int*)  d_in[2];
    const int*   ei       = (const int*)  d_in[3];
    const float* emb      = (const float*)d_in[4];
    const float* mlp_w1   = (const float*)d_in[5];
    const float* mlp_b1   = (const float*)d_in[6];
    const float* mlp_w2   = (const float*)d_in[7];
    const float* mlp_b2   = (const float*)d_in[8];
    const float* lin1_w   = (const float*)d_in[9];
    const float* lin2_w   = (const float*)d_in[10];
    const float* lin2_b   = (const float*)d_in[11];
    const float* int_lin_w = (const float*)d_in[12];
    const float* int_lin_b = (const float*)d_in[13];
    const float* pool_w   = (const float*)d_in[14];
    const float* pool_b   = (const float*)d_in[15];
    float* out = (float*)d_out;

    float *p_rbf, *p_C, *p_h, *p_t1, *p_W, *p_hp, *p_agg, *p_x, *p_pool, *p_cnt;
    cudaGetSymbolAddress((void**)&p_rbf,  g_rbf);
    cudaGetSymbolAddress((void**)&p_C,    g_Ccut);
    cudaGetSymbolAddress((void**)&p_h,    g_h);
    cudaGetSymbolAddress((void**)&p_t1,   g_t1);
    cudaGetSymbolAddress((void**)&p_W,    g_W);
    cudaGetSymbolAddress((void**)&p_hp,   g_hp);
    cudaGetSymbolAddress((void**)&p_agg,  g_agg);
    cudaGetSymbolAddress((void**)&p_x,    g_x);
    cudaGetSymbolAddress((void**)&p_pool, g_pool);
    cudaGetSymbolAddress((void**)&p_cnt,  g_cnt);

    edge_geom_kernel<<<(NEDGES + 255) / 256, 256>>>(pos, ei, p_rbf, p_C);
    {
        size_t tot = (size_t)NATOMS * NH;
        init_h_kernel<<<(unsigned)((tot + 255) / 256), 256>>>(z, emb, p_h);
    }

    dim3 blk(256);
    dim3 gE((NH + 127) / 128, (NEDGES + 127) / 128);
    dim3 gN((NH + 127) / 128, (NATOMS + 127) / 128);
    dim3 gB((NH + 127) / 128, (NB + 127) / 128);

    for (int k = 0; k < NL; k++) {
        const float* w1  = mlp_w1 + (size_t)k * NG * NH;
        const float* b1  = mlp_b1 + (size_t)k * NH;
        const float* w2  = mlp_w2 + (size_t)k * NH * NH;
        const float* b2  = mlp_b2 + (size_t)k * NH;
        const float* l1  = lin1_w + (size_t)k * NH * NH;
        const float* l2  = lin2_w + (size_t)k * NH * NH;
        const float* l2b = lin2_b + (size_t)k * NH;
        const float* il  = int_lin_w + (size_t)k * NH * NH;
        const float* ilb = int_lin_b + (size_t)k * NH;

        // t1 = ssp(rbf @ w1 + b1)           [E,H]
        gemm_tc<1><<<gE, blk>>>(p_rbf, w1, b1, p_t1, NEDGES, NH, NG, nullptr, nullptr);
        // W = (t1 @ w2 + b2) * C[:,None]    [E,H]
        gemm_tc<2><<<gE, blk>>>(p_t1, w2, b2, p_W, NEDGES, NH, NH, p_C, nullptr);
        // hp = h @ lin1                     [N,H]
        gemm_tc<3><<<gN, blk>>>(p_h, l1, nullptr, p_hp, NATOMS, NH, NH, nullptr, nullptr);
        // agg = scatter_add(hp[src] * W, dst)
        cudaMemsetAsync(p_agg, 0, (size_t)NATOMS * NH * sizeof(float));
        {
            size_t tot = (size_t)NEDGES * (NH / 4);
            scatter_kernel<<<(unsigned)((tot + 255) / 256), 256>>>(ei, p_hp, p_W, p_agg);
        }
        // x = ssp(agg @ lin2 + lin2_b)      [N,H]
        gemm_tc<1><<<gN, blk>>>(p_agg, l2, l2b, p_x, NATOMS, NH, NH, nullptr, nullptr);
        // h += x @ int_lin + int_lin_b      [N,H]
        gemm_tc<4><<<gN, blk>>>(p_x, il, ilb, nullptr, NATOMS, NH, NH, nullptr, p_h);
    }

    cudaMemsetAsync(p_pool, 0, (size_t)NB * NH * sizeof(float));
    cudaMemsetAsync(p_cnt, 0, NB * sizeof(float));
    {
        size_t tot = (size_t)NATOMS * (NH / 4);
        pool_sum_kernel<<<(unsigned)((tot + 255) / 256), 256>>>(batch, p_h, p_pool);
    }
    pool_cnt_kernel<<<(NATOMS + 255) / 256, 256>>>(batch, p_cnt);
    pool_div_kernel<<<(NB * NH + 255) / 256, 256>>>(p_pool, p_cnt);

    // out = pooled @ pool_w + pool_b       [B,H]
    gemm_tc<0><<<gB, blk>>>(p_pool, pool_w, pool_b, out, NB, NH, NH, nullptr, nullptr);
}

// round 17
// speedup vs baseline: 1.3189x; 1.3189x over previous
#include <cuda_runtime.h>
#include <cuda_fp16.h>
#include <math.h>
#include <stdio.h>

#define NATOMS 10000
#define NEDGES 64000
#define NB     128
#define NH     600
#define NG     50
#define NGP    64          // padded gaussian dim (K of gemm1)
#define NL     6
#define LOG2F_C 0.6931471805599453f
#define PI_F    3.14159265358979323846f

// ---------------- scratch (device globals; no allocation allowed) ----------------
__device__ __align__(16) __half g_rbfh[(size_t)NEDGES * NGP];
__device__ __align__(16) __half g_w1h [(size_t)NL * NGP * NH];
__device__ __align__(16) __half g_w2h [(size_t)NL * NH * NH];
__device__ __align__(16) __half g_l1h [(size_t)NL * NH * NH];
__device__ __align__(16) __half g_l2h [(size_t)NL * NH * NH];
__device__ __align__(16) __half g_ilh [(size_t)NL * NH * NH];
__device__ __align__(16) __half g_pwh [(size_t)NH * NH];
__device__ __align__(16) __half g_hh  [(size_t)NATOMS * NH];
__device__ __align__(16) __half g_t1h [(size_t)NEDGES * NH];
__device__ __align__(16) __half g_Wh  [(size_t)NEDGES * NH];
__device__ __align__(16) __half g_hph [(size_t)NATOMS * NH];
__device__ __align__(16) __half g_aggh[(size_t)NATOMS * NH];
__device__ __align__(16) __half g_xh  [(size_t)NATOMS * NH];
__device__ __align__(16) __half g_plh [(size_t)NB * NH];
__device__ float g_Ccut[NEDGES];
__device__ float g_h   [(size_t)NATOMS * NH];
__device__ float g_agg [(size_t)NATOMS * NH];
__device__ float g_pool[(size_t)NB * NH];
__device__ float g_cnt [NB];

__device__ __forceinline__ float ssp(float x) {
    return log1pf(expf(-fabsf(x))) + fmaxf(x, 0.0f) - LOG2F_C;
}

__device__ __forceinline__ void mma_f16(float* c, const unsigned* a, unsigned b0, unsigned b1) {
    asm volatile(
        "mma.sync.aligned.m16n8k16.row.col.f32.f16.f16.f32 "
        "{%0,%1,%2,%3}, {%4,%5,%6,%7}, {%8,%9}, {%0,%1,%2,%3};\n"
        : "+f"(c[0]), "+f"(c[1]), "+f"(c[2]), "+f"(c[3])
        : "r"(a[0]), "r"(a[1]), "r"(a[2]), "r"(a[3]), "r"(b0), "r"(b1));
}

__device__ __forceinline__ void ldm_x4(unsigned* r, unsigned addr) {
    asm volatile("ldmatrix.sync.aligned.m8n8.x4.shared.b16 {%0,%1,%2,%3}, [%4];"
                 : "=r"(r[0]), "=r"(r[1]), "=r"(r[2]), "=r"(r[3]) : "r"(addr));
}

__device__ __forceinline__ void ldm_x4_t(unsigned* r, unsigned addr) {
    asm volatile("ldmatrix.sync.aligned.m8n8.x4.trans.shared.b16 {%0,%1,%2,%3}, [%4];"
                 : "=r"(r[0]), "=r"(r[1]), "=r"(r[2]), "=r"(r[3]) : "r"(addr));
}

__device__ __forceinline__ void cpa16(unsigned dst, const void* src, int sz) {
    asm volatile("cp.async.cg.shared.global [%0], [%1], 16, %2;"
                 :: "r"(dst), "l"(src), "r"(sz));
}
#define CP_COMMIT() asm volatile("cp.async.commit_group;")
#define CP_WAIT0()  asm volatile("cp.async.wait_group 0;")

// ---------------- conversions ----------------
__global__ void conv_f2h(const float* __restrict__ src, __half* __restrict__ dst, int n) {
    int i = blockIdx.x * blockDim.x + threadIdx.x;
    if (i < n) dst[i] = __float2half(src[i]);
}

__global__ void conv_w1(const float* __restrict__ w1, __half* __restrict__ dst) {
    int i = blockIdx.x * blockDim.x + threadIdx.x;           // over NL*NGP*NH
    if (i >= NL * NGP * NH) return;
    int c = i % NH;
    int r = (i / NH) % NGP;
    int l = i / (NGP * NH);
    dst[i] = (r < NG) ? __float2half(w1[((size_t)l * NG + r) * NH + c]) : __half(0);
}

// ---------------- edge geometry (writes padded fp16 rbf) ----------------
__global__ void edge_geom_kernel(const float* __restrict__ pos,
                                 const int* __restrict__ ei,
                                 __half* __restrict__ rbf,
                                 float* __restrict__ Ccut) {
    int e = blockIdx.x * blockDim.x + threadIdx.x;
    if (e >= NEDGES) return;
    int s = ei[e];
    int t = ei[NEDGES + e];
    float dx = pos[3*s+0] - pos[3*t+0];
    float dy = pos[3*s+1] - pos[3*t+1];
    float dz = pos[3*s+2] - pos[3*t+2];
    float d = sqrtf(dx*dx + dy*dy + dz*dz + 1e-12f);
    Ccut[e] = 0.5f * (cosf(d * (PI_F / 10.0f)) + 1.0f);
    const float delta = 10.0f / 49.0f;
    const float coeff = -0.5f / (delta * delta);
    #pragma unroll
    for (int g = 0; g < NGP; g++) {
        float u = d - (float)g * delta;
        float v = (g < NG) ? expf(coeff * u * u) : 0.0f;
        rbf[(size_t)e * NGP + g] = __float2half(v);
    }
}

// ---------------- h init ----------------
__global__ void init_h_kernel(const int* __restrict__ z,
                              const float* __restrict__ emb,
                              float* __restrict__ h, __half* __restrict__ hh) {
    size_t idx = (size_t)blockIdx.x * blockDim.x + threadIdx.x;
    if (idx >= (size_t)NATOMS * NH) return;
    int n = (int)(idx / NH);
    int c = (int)(idx - (size_t)n * NH);
    float v = emb[(size_t)z[n] * NH + c];
    h[idx] = v;
    hh[idx] = __float2half(v);
}

// ---------------- fp16 GEMM: cp.async pipeline, 128x128x32 tile -------------
// C[M,N] = A[M,K] @ B[K,N], A,B fp16 row-major global.
// A smem: [128 rows][64B], chunk swizzle c^((row>>1)&3)  -> ldmatrix conflict-free
// B smem: [32 rows][256B], chunk swizzle c^(row&7)       -> trans-ldmatrix conflict-free
// Two stages, cp.async.cg 16B with zfill tails, ONE __syncthreads per 32-k tile.
// EPI 0: float out = v+bias  1: half out = ssp(v+bias)  2: half out = (v+bias)*rowmul
// EPI 3: half out = v        4: accp += v+bias (fp32) and acch = half(new)
#define KT 32
#define A_BYTES (128 * 64)
#define B_BYTES (32 * 256)
#define STG_BYTES (A_BYTES + B_BYTES)

template<int EPI>
__global__ __launch_bounds__(256, 2)
void gemm_tc(const __half* __restrict__ A, const __half* __restrict__ Bm,
             const float* __restrict__ bias, void* __restrict__ CoutV,
             int M, int Nn, int K,
             const float* __restrict__ rowmul, float* __restrict__ accp,
             __half* __restrict__ acch)
{
    __shared__ __align__(16) char smem[2 * STG_BYTES];

    const int tid  = threadIdx.x;
    const int lane = tid & 31;
    const int warp = tid >> 5;
    const int wm = (warp >> 2) * 64;   // 0/64
    const int wn = (warp &  3) * 32;   // 0/32/64/96
    const int g = lane >> 2;
    const int t = lane & 3;
    const int m0 = blockIdx.y * 128;
    const int n0 = blockIdx.x * 128;
    const unsigned smBase = (unsigned)__cvta_generic_to_shared(smem);

    float acc[4][4][4];
    #pragma unroll
    for (int i = 0; i < 4; i++)
        #pragma unroll
        for (int j = 0; j < 4; j++)
            #pragma unroll
            for (int r = 0; r < 4; r++) acc[i][j][r] = 0.0f;

    // staging indices
    const int arI[2] = { tid >> 2, (tid + 256) >> 2 };   // A row 0..127
    const int acI[2] = { tid & 3, (tid + 256) & 3 };     // A chunk 0..3
    const int bkI[2] = { tid >> 4, (tid + 256) >> 4 };   // B row 0..31
    const int bcI[2] = { tid & 15, (tid + 256) & 15 };   // B chunk 0..15

    auto stage = [&](int kt, int s) {
        unsigned ab = smBase + s * STG_BYTES;
        unsigned bb = ab + A_BYTES;
        #pragma unroll
        for (int i = 0; i < 2; i++) {
            int r = arI[i], c = acI[i];
            unsigned dst = ab + r * 64 + ((c ^ ((r >> 1) & 3)) << 4);
            int row = m0 + r, col = kt + c * 8;
            int sz = (row < M && col < K) ? 16 : 0;
            const __half* src = A + (sz ? ((size_t)row * K + col) : 0);
            cpa16(dst, src, sz);
            int k = bkI[i], cc = bcI[i];
            unsigned bdst = bb + k * 256 + ((cc ^ (k & 7)) << 4);
            int brow = kt + k, bcol = n0 + cc * 8;
            int bsz = (brow < K && bcol < Nn) ? 16 : 0;
            const __half* bsrc = Bm + (bsz ? ((size_t)brow * Nn + bcol) : 0);
            cpa16(bdst, bsrc, bsz);
        }
        CP_COMMIT();
    };

    // fragment address constants
    const int m_ln = wm + ((lane >> 3) & 1) * 8 + (lane & 7);   // + mf*16
    const int aHiC = lane >> 4;                                 // chunk add 0/1
    const int bj = lane >> 3, br = lane & 7;
    const int bChunkBase = (wn >> 3) + (bj >> 1);               // + pp*2
    const int bRowBase = (bj & 1) * 8 + br;                     // + kk

    const int nt = (K + KT - 1) / KT;
    stage(0, 0);

    int p = 0;
    for (int ti = 0; ti < nt; ti++) {
        CP_WAIT0();
        __syncthreads();
        if (ti + 1 < nt) stage((ti + 1) * KT, p ^ 1);

        unsigned ab = smBase + p * STG_BYTES;
        unsigned bb = ab + A_BYTES;

        #pragma unroll
        for (int kk = 0; kk < KT; kk += 16) {
            unsigned bfr[2][4];
            #pragma unroll
            for (int pp = 0; pp < 2; pp++) {
                int row = bRowBase + kk;
                int ch = (bChunkBase + pp * 2) ^ (row & 7);
                ldm_x4_t(bfr[pp], bb + row * 256 + (ch << 4));
            }
            unsigned af[4][4];
            #pragma unroll
            for (int mf = 0; mf < 4; mf++) {
                int row = m_ln + mf * 16;
                int ch = ((kk >> 3) + aHiC) ^ ((row >> 1) & 3);
                ldm_x4(af[mf], ab + row * 64 + (ch << 4));
            }
            #pragma unroll
            for (int mf = 0; mf < 4; mf++)
                #pragma unroll
                for (int nf = 0; nf < 4; nf++)
                    mma_f16(acc[mf][nf], af[mf],
                            bfr[nf >> 1][(nf & 1) * 2], bfr[nf >> 1][(nf & 1) * 2 + 1]);
        }
        p ^= 1;
    }

    // epilogue
    #pragma unroll
    for (int mf = 0; mf < 4; mf++) {
        #pragma unroll
        for (int nf = 0; nf < 4; nf++) {
            int rb = m0 + wm + mf * 16 + g;
            int cb = n0 + wn + nf * 8 + 2 * t;
            if (cb >= Nn) continue;
            float b0 = (EPI != 3) ? bias[cb] : 0.0f;
            float b1 = (EPI != 3) ? bias[cb + 1] : 0.0f;
            #pragma unroll
            for (int half_ = 0; half_ < 2; half_++) {
                int mm = rb + half_ * 8;
                if (mm >= M) continue;
                float v0 = acc[mf][nf][half_ * 2 + 0];
                float v1 = acc[mf][nf][half_ * 2 + 1];
                size_t o = (size_t)mm * Nn + cb;
                if (EPI == 0) {
                    ((float*)CoutV)[o]     = v0 + b0;
                    ((float*)CoutV)[o + 1] = v1 + b1;
                } else if (EPI == 1) {
                    __half2 hv = __floats2half2_rn(ssp(v0 + b0), ssp(v1 + b1));
                    *(__half2*)((__half*)CoutV + o) = hv;
                } else if (EPI == 2) {
                    float cm = rowmul[mm];
                    __half2 hv = __floats2half2_rn((v0 + b0) * cm, (v1 + b1) * cm);
                    *(__half2*)((__half*)CoutV + o) = hv;
                } else if (EPI == 3) {
                    __half2 hv = __floats2half2_rn(v0, v1);
                    *(__half2*)((__half*)CoutV + o) = hv;
                } else {  // EPI == 4
                    float n0v = accp[o]     + v0 + b0;
                    float n1v = accp[o + 1] + v1 + b1;
                    accp[o] = n0v; accp[o + 1] = n1v;
                    *(__half2*)(acch + o) = __floats2half2_rn(n0v, n1v);
                }
            }
        }
    }
}

// ---------------- CFConv scatter (fp16 inputs, fp32 atomics) ----------------
__global__ void scatter_kernel(const int* __restrict__ ei,
                               const __half* __restrict__ hp,
                               const __half* __restrict__ W,
                               float* __restrict__ agg) {
    size_t idx = (size_t)blockIdx.x * blockDim.x + threadIdx.x;
    const int Q = NH / 8;  // 75
    if (idx >= (size_t)NEDGES * Q) return;
    int e = (int)(idx / Q);
    int j = (int)(idx - (size_t)e * Q) * 8;
    int s = ei[e];
    int t = ei[NEDGES + e];
    const __half2* hv = (const __half2*)&hp[(size_t)s * NH + j];
    const __half2* wv = (const __half2*)&W[(size_t)e * NH + j];
    float* dst = &agg[(size_t)t * NH + j];
    #pragma unroll
    for (int w = 0; w < 4; w++) {
        float2 pr = __half22float2(__hmul2(hv[w], wv[w]));
        atomicAdd(dst + 2 * w + 0, pr.x);
        atomicAdd(dst + 2 * w + 1, pr.y);
    }
}

__global__ void conv_agg(const float* __restrict__ agg, __half* __restrict__ aggh) {
    size_t idx = (size_t)blockIdx.x * blockDim.x + threadIdx.x;
    if (idx >= (size_t)NATOMS * NH) return;
    aggh[idx] = __float2half(agg[idx]);
}

// ---------------- pooling ----------------
__global__ void pool_sum_kernel(const int* __restrict__ batch,
                                const float* __restrict__ h,
                                float* __restrict__ psum) {
    size_t idx = (size_t)blockIdx.x * blockDim.x + threadIdx.x;
    const int Q = NH / 4;
    if (idx >= (size_t)NATOMS * Q) return;
    int n = (int)(idx / Q);
    int c4 = (int)(idx - (size_t)n * Q) * 4;
    float4 hv = *(const float4*)&h[(size_t)n * NH + c4];
    float* dst = &psum[(size_t)batch[n] * NH + c4];
    atomicAdd(dst + 0, hv.x);
    atomicAdd(dst + 1, hv.y);
    atomicAdd(dst + 2, hv.z);
    atomicAdd(dst + 3, hv.w);
}

__global__ void pool_cnt_kernel(const int* __restrict__ batch, float* __restrict__ cnt) {
    int n = blockIdx.x * blockDim.x + threadIdx.x;
    if (n >= NATOMS) return;
    atomicAdd(&cnt[batch[n]], 1.0f);
}

__global__ void pool_div_kernel(float* __restrict__ psum, const float* __restrict__ cnt,
                                __half* __restrict__ ph) {
    int idx = blockIdx.x * blockDim.x + threadIdx.x;
    if (idx >= NB * NH) return;
    int b = idx / NH;
    float v = psum[idx] / fmaxf(cnt[b], 1.0f);
    psum[idx] = v;
    ph[idx] = __float2half(v);
}

// ---------------- host launcher ----------------
extern "C" void kernel_launch(void* const* d_in, const int* in_sizes, int n_in,
                              void* d_out, int out_size) {
    const int*   z        = (const int*)  d_in[0];
    const float* pos      = (const float*)d_in[1];
    const int*   batch    = (const int*)  d_in[2];
    const int*   ei       = (const int*)  d_in[3];
    const float* emb      = (const float*)d_in[4];
    const float* mlp_w1   = (const float*)d_in[5];
    const float* mlp_b1   = (const float*)d_in[6];
    const float* mlp_w2   = (const float*)d_in[7];
    const float* mlp_b2   = (const float*)d_in[8];
    const float* lin1_w   = (const float*)d_in[9];
    const float* lin2_w   = (const float*)d_in[10];
    const float* lin2_b   = (const float*)d_in[11];
    const float* int_lin_w = (const float*)d_in[12];
    const float* int_lin_b = (const float*)d_in[13];
    const float* pool_w   = (const float*)d_in[14];
    const float* pool_b   = (const float*)d_in[15];
    float* out = (float*)d_out;

    float *p_C, *p_h, *p_agg, *p_pool, *p_cnt;
    __half *p_rbfh, *p_w1h, *p_w2h, *p_l1h, *p_l2h, *p_ilh, *p_pwh;
    __half *p_hh, *p_t1h, *p_Wh, *p_hph, *p_aggh, *p_xh, *p_plh;
    cudaGetSymbolAddress((void**)&p_C,    g_Ccut);
    cudaGetSymbolAddress((void**)&p_h,    g_h);
    cudaGetSymbolAddress((void**)&p_agg,  g_agg);
    cudaGetSymbolAddress((void**)&p_pool, g_pool);
    cudaGetSymbolAddress((void**)&p_cnt,  g_cnt);
    cudaGetSymbolAddress((void**)&p_rbfh, g_rbfh);
    cudaGetSymbolAddress((void**)&p_w1h,  g_w1h);
    cudaGetSymbolAddress((void**)&p_w2h,  g_w2h);
    cudaGetSymbolAddress((void**)&p_l1h,  g_l1h);
    cudaGetSymbolAddress((void**)&p_l2h,  g_l2h);
    cudaGetSymbolAddress((void**)&p_ilh,  g_ilh);
    cudaGetSymbolAddress((void**)&p_pwh,  g_pwh);
    cudaGetSymbolAddress((void**)&p_hh,   g_hh);
    cudaGetSymbolAddress((void**)&p_t1h,  g_t1h);
    cudaGetSymbolAddress((void**)&p_Wh,   g_Wh);
    cudaGetSymbolAddress((void**)&p_hph,  g_hph);
    cudaGetSymbolAddress((void**)&p_aggh, g_aggh);
    cudaGetSymbolAddress((void**)&p_xh,   g_xh);
    cudaGetSymbolAddress((void**)&p_plh,  g_plh);

    // weight conversions (fp32 -> fp16)
    {
        int nW = NL * NH * NH;
        conv_f2h<<<(nW + 255) / 256, 256>>>(mlp_w2, p_w2h, nW);
        conv_f2h<<<(nW + 255) / 256, 256>>>(lin1_w, p_l1h, nW);
        conv_f2h<<<(nW + 255) / 256, 256>>>(lin2_w, p_l2h, nW);
        conv_f2h<<<(nW + 255) / 256, 256>>>(int_lin_w, p_ilh, nW);
        conv_f2h<<<(NH * NH + 255) / 256, 256>>>(pool_w, p_pwh, NH * NH);
        conv_w1<<<(NL * NGP * NH + 255) / 256, 256>>>(mlp_w1, p_w1h);
    }

    edge_geom_kernel<<<(NEDGES + 255) / 256, 256>>>(pos, ei, p_rbfh, p_C);
    {
        size_t tot = (size_t)NATOMS * NH;
        init_h_kernel<<<(unsigned)((tot + 255) / 256), 256>>>(z, emb, p_h, p_hh);
    }

    dim3 blk(256);
    dim3 gE((NH + 127) / 128, (NEDGES + 127) / 128);
    dim3 gN((NH + 127) / 128, (NATOMS + 127) / 128);
    dim3 gB((NH + 127) / 128, 1);

    for (int k = 0; k < NL; k++) {
        const __half* w1  = p_w1h + (size_t)k * NGP * NH;
        const float*  b1  = mlp_b1 + (size_t)k * NH;
        const __half* w2  = p_w2h + (size_t)k * NH * NH;
        const float*  b2  = mlp_b2 + (size_t)k * NH;
        const __half* l1  = p_l1h + (size_t)k * NH * NH;
        const __half* l2  = p_l2h + (size_t)k * NH * NH;
        const float*  l2b = lin2_b + (size_t)k * NH;
        const __half* il  = p_ilh + (size_t)k * NH * NH;
        const float*  ilb = int_lin_b + (size_t)k * NH;

        // t1 = ssp(rbf @ w1 + b1)            [E,H] fp16
        gemm_tc<1><<<gE, blk>>>(p_rbfh, w1, b1, p_t1h, NEDGES, NH, NGP, nullptr, nullptr, nullptr);
        // W = (t1 @ w2 + b2) * C[:,None]     [E,H] fp16
        gemm_tc<2><<<gE, blk>>>(p_t1h, w2, b2, p_Wh, NEDGES, NH, NH, p_C, nullptr, nullptr);
        // hp = h @ lin1                      [N,H] fp16
        gemm_tc<3><<<gN, blk>>>(p_hh, l1, nullptr, p_hph, NATOMS, NH, NH, nullptr, nullptr, nullptr);
        // agg = scatter_add(hp[src]*W, dst)  fp32 atomics
        cudaMemsetAsync(p_agg, 0, (size_t)NATOMS * NH * sizeof(float));
        {
            size_t tot = (size_t)NEDGES * (NH / 8);
            scatter_kernel<<<(unsigned)((tot + 255) / 256), 256>>>(ei, p_hph, p_Wh, p_agg);
        }
        {
            size_t tot = (size_t)NATOMS * NH;
            conv_agg<<<(unsigned)((tot + 255) / 256), 256>>>(p_agg, p_aggh);
        }
        // x = ssp(agg @ lin2 + lin2_b)       [N,H] fp16
        gemm_tc<1><<<gN, blk>>>(p_aggh, l2, l2b, p_xh, NATOMS, NH, NH, nullptr, nullptr, nullptr);
        // h += x @ int_lin + int_lin_b       (fp32 master + fp16 copy)
        gemm_tc<4><<<gN, blk>>>(p_xh, il, ilb, nullptr, NATOMS, NH, NH, nullptr, p_h, p_hh);
    }

    cudaMemsetAsync(p_pool, 0, (size_t)NB * NH * sizeof(float));
    cudaMemsetAsync(p_cnt, 0, NB * sizeof(float));
    {
        size_t tot = (size_t)NATOMS * (NH / 4);
        pool_sum_kernel<<<(unsigned)((tot + 255) / 256), 256>>>(batch, p_h, p_pool);
    }
    pool_cnt_kernel<<<(NATOMS + 255) / 256, 256>>>(batch, p_cnt);
    pool_div_kernel<<<(NB * NH + 255) / 256, 256>>>(p_pool, p_cnt, p_plh);

    // out = pooled @ pool_w + pool_b        [B,H] fp32
    gemm_tc<0><<<gB, blk>>>(p_plh, p_pwh, pool_b, out, NB, NH, NH, nullptr, nullptr, nullptr);
}